// round 2
// baseline (speedup 1.0000x reference)
#include <cuda_runtime.h>
#include <cuda_bf16.h>

#define Bsz    64
#define Hd     1024
#define NV     101          // tokens incl. start symbol (start = 100)
#define UMX    256
#define NSTEPS 257
#define G3     3072         // 3*Hd
#define OD     1024
#define NCTA   128
#define NTHR   256
#define ETW    104          // embed-transpose padded width

typedef unsigned long long u64;

// ---------------- static device scratch (no runtime allocation) ----------------
__device__ __align__(16) float g_T[NV * G3];            // layer0 gi table (incl. b_ih0)
__device__ __align__(16) float g_ET[Hd * ETW];          // embed transposed [k][v]
__device__ __align__(16) float g_st[2][3][Hd * Bsz];    // states k-major: [buf][layer][k*64+b]
__device__ unsigned g_bar;                              // ticket barrier counter

// ---------------- grid barrier (all NCTA CTAs co-resident, 1/SM) ----------------
__device__ __forceinline__ void gridbar() {
    __syncthreads();
    if (threadIdx.x == 0) {
        __threadfence();
        unsigned ticket = atomicAdd(&g_bar, 1u) + 1u;
        unsigned target = ((ticket + NCTA - 1u) / NCTA) * NCTA;
        while (*((volatile unsigned*)&g_bar) < target) { __nanosleep(64); }
    }
    __syncthreads();
    __threadfence();
}

// ---------------- packed f32x2 helpers ----------------
__device__ __forceinline__ u64 pk2(float v) {
    u64 r;
    asm("mov.b64 %0, {%1, %1};" : "=l"(r) : "f"(v));
    return r;
}
__device__ __forceinline__ void fma2(u64& d, u64 a, u64 b) {
    asm("fma.rn.f32x2 %0, %1, %2, %0;" : "+l"(d) : "l"(a), "l"(b));
}
__device__ __forceinline__ float2 upk2(u64 v) {
    float lo, hi;
    asm("mov.b64 {%0, %1}, %2;" : "=f"(lo), "=f"(hi) : "l"(v));
    return make_float2(lo, hi);
}
__device__ __forceinline__ float sigm(float t) { return 1.0f / (1.0f + expf(-t)); }

// ================================================================================
__global__ void __launch_bounds__(NTHR, 1)
decoder_kernel(const int*   __restrict__ y,
               const float* __restrict__ embed,
               const float* __restrict__ W_ih,
               const float* __restrict__ W_hh,
               const float* __restrict__ b_ih,
               const float* __restrict__ b_hh,
               const float* __restrict__ init_state,
               const float* __restrict__ lin_W,
               const float* __restrict__ lin_b,
               float*       __restrict__ out)
{
    const int tid = threadIdx.x;
    const int j   = (blockIdx.x << 3) + (tid >> 5);   // 0..1023 (row / hidden index)
    const int b0  = (tid & 31) << 1;                  // batch pair base
    const int gt  = blockIdx.x * NTHR + tid;

    // ---------------- prologue: init states + transpose embed ----------------
    for (int idx = gt; idx < 3 * Hd * Bsz; idx += NCTA * NTHR) {
        int l = idx / (Hd * Bsz);
        int r = idx - l * (Hd * Bsz);
        g_st[1][l][r] = init_state[l * Hd + (r >> 6)];
    }
    for (int idx = gt; idx < Hd * ETW; idx += NCTA * NTHR) {
        int k = idx / ETW, v = idx - k * ETW;
        g_ET[idx] = (v < NV) ? embed[(size_t)v * Hd + k] : 0.0f;
    }
    gridbar();

    // ---------------- token table: T[v][g*H+j] = embed[v].Wih0_row + b_ih0 ----------------
    {
        const float* w0 = W_ih + (size_t)j * Hd;              // layer0, gate r
        const float* w1 = W_ih + (size_t)(Hd + j) * Hd;       // gate z
        const float* w2 = W_ih + (size_t)(2 * Hd + j) * Hd;   // gate n
        for (int vp = (tid & 31); vp < ETW / 2; vp += 32) {
            const int v0 = vp << 1;
            u64 a0 = 0, a1 = 0, a2 = 0;
#pragma unroll 2
            for (int k = 0; k < Hd; k += 4) {
                float4 wa = *(const float4*)(w0 + k);
                float4 wb = *(const float4*)(w1 + k);
                float4 wc = *(const float4*)(w2 + k);
#pragma unroll
                for (int kk = 0; kk < 4; ++kk) {
                    u64 ev = *(const u64*)(g_ET + (size_t)(k + kk) * ETW + v0);
                    fma2(a0, pk2(((const float*)&wa)[kk]), ev);
                    fma2(a1, pk2(((const float*)&wb)[kk]), ev);
                    fma2(a2, pk2(((const float*)&wc)[kk]), ev);
                }
            }
            float2 t0 = upk2(a0), t1 = upk2(a1), t2 = upk2(a2);
            float br = b_ih[j], bz = b_ih[Hd + j], bn = b_ih[2 * Hd + j];
            if (v0 < NV) {
                g_T[(size_t)v0 * G3 + j]          = t0.x + br;
                g_T[(size_t)v0 * G3 + Hd + j]     = t1.x + bz;
                g_T[(size_t)v0 * G3 + 2 * Hd + j] = t2.x + bn;
            }
            if (v0 + 1 < NV) {
                g_T[(size_t)(v0 + 1) * G3 + j]          = t0.y + br;
                g_T[(size_t)(v0 + 1) * G3 + Hd + j]     = t1.y + bz;
                g_T[(size_t)(v0 + 1) * G3 + 2 * Hd + j] = t2.y + bn;
            }
        }
    }
    gridbar();

    // ---------------- autoregressive step loop ----------------
    for (int u = 0; u < NSTEPS; ++u) {
        const int cur = u & 1, prv = cur ^ 1;

        // ===== phase A: output linear of step u-1 (reads st[prv][2]) =====
        if (u > 0) {
            const float* h2 = g_st[prv][2];
            const float* w  = lin_W + (size_t)j * Hd;
            u64 acc = 0;
#pragma unroll 2
            for (int k = 0; k < Hd; k += 4) {
                float4 wv = *(const float4*)(w + k);
#pragma unroll
                for (int kk = 0; kk < 4; ++kk)
                    fma2(acc, pk2(((const float*)&wv)[kk]),
                         *(const u64*)(h2 + (size_t)(k + kk) * Bsz + b0));
            }
            float2 t  = upk2(acc);
            float  bb = lin_b[j];
            size_t o0 = (size_t)b0 * NSTEPS * OD + (size_t)(u - 1) * OD + j;
            out[o0]                      = t.x + bb;
            out[o0 + (size_t)NSTEPS * OD] = t.y + bb;
        }

        // ===== phase A: layer 0 (Whh GEMM only; gi gathered from table) =====
        {
            const float* hp = g_st[prv][0];
            const float* w0 = W_hh + (size_t)j * Hd;
            const float* w1 = W_hh + (size_t)(Hd + j) * Hd;
            const float* w2 = W_hh + (size_t)(2 * Hd + j) * Hd;
            u64 aR = 0, aZ = 0, aN = 0;
#pragma unroll 2
            for (int k = 0; k < Hd; k += 4) {
                float4 wa = *(const float4*)(w0 + k);
                float4 wb = *(const float4*)(w1 + k);
                float4 wc = *(const float4*)(w2 + k);
#pragma unroll
                for (int kk = 0; kk < 4; ++kk) {
                    u64 hv = *(const u64*)(hp + (size_t)(k + kk) * Bsz + b0);
                    fma2(aR, pk2(((const float*)&wa)[kk]), hv);
                    fma2(aZ, pk2(((const float*)&wb)[kk]), hv);
                    fma2(aN, pk2(((const float*)&wc)[kk]), hv);
                }
            }
            int tk0 = (u == 0) ? (NV - 1) : y[b0 * UMX + (u - 1)];
            int tk1 = (u == 0) ? (NV - 1) : y[(b0 + 1) * UMX + (u - 1)];
            const float* T0 = g_T + (size_t)tk0 * G3 + j;
            const float* T1 = g_T + (size_t)tk1 * G3 + j;
            float2 ghr = upk2(aR), ghz = upk2(aZ), ghn = upk2(aN);
            float  bhr = b_hh[j], bhz = b_hh[Hd + j], bhn = b_hh[2 * Hd + j];
            float2 ho  = *(const float2*)(hp + (size_t)j * Bsz + b0);
            float2 hn;
            {
                float r = sigm(T0[0]      + ghr.x + bhr);
                float z = sigm(T0[Hd]     + ghz.x + bhz);
                float n = tanhf(T0[2 * Hd] + r * (ghn.x + bhn));
                hn.x = (1.0f - z) * n + z * ho.x;
            }
            {
                float r = sigm(T1[0]      + ghr.y + bhr);
                float z = sigm(T1[Hd]     + ghz.y + bhz);
                float n = tanhf(T1[2 * Hd] + r * (ghn.y + bhn));
                hn.y = (1.0f - z) * n + z * ho.y;
            }
            *(float2*)(g_st[cur][0] + (size_t)j * Bsz + b0) = hn;
        }
        gridbar();

        // ===== phases B, C: layers 1, 2 (full gi + gh GEMMs) =====
#pragma unroll
        for (int l = 1; l < 3; ++l) {
            const float* xx = g_st[cur][l - 1];
            const float* hp = g_st[prv][l];
            const float* Wi = W_ih + (size_t)l * G3 * Hd;
            const float* Wh = W_hh + (size_t)l * G3 * Hd;
            const float* wi0 = Wi + (size_t)j * Hd;
            const float* wi1 = Wi + (size_t)(Hd + j) * Hd;
            const float* wi2 = Wi + (size_t)(2 * Hd + j) * Hd;
            const float* wh0 = Wh + (size_t)j * Hd;
            const float* wh1 = Wh + (size_t)(Hd + j) * Hd;
            const float* wh2 = Wh + (size_t)(2 * Hd + j) * Hd;
            u64 iR = 0, iZ = 0, iN = 0, hR = 0, hZ = 0, hN = 0;
#pragma unroll 2
            for (int k = 0; k < Hd; k += 4) {
                float4 wia = *(const float4*)(wi0 + k);
                float4 wib = *(const float4*)(wi1 + k);
                float4 wic = *(const float4*)(wi2 + k);
                float4 wha = *(const float4*)(wh0 + k);
                float4 whb = *(const float4*)(wh1 + k);
                float4 whc = *(const float4*)(wh2 + k);
#pragma unroll
                for (int kk = 0; kk < 4; ++kk) {
                    u64 xv = *(const u64*)(xx + (size_t)(k + kk) * Bsz + b0);
                    u64 hv = *(const u64*)(hp + (size_t)(k + kk) * Bsz + b0);
                    fma2(iR, pk2(((const float*)&wia)[kk]), xv);
                    fma2(iZ, pk2(((const float*)&wib)[kk]), xv);
                    fma2(iN, pk2(((const float*)&wic)[kk]), xv);
                    fma2(hR, pk2(((const float*)&wha)[kk]), hv);
                    fma2(hZ, pk2(((const float*)&whb)[kk]), hv);
                    fma2(hN, pk2(((const float*)&whc)[kk]), hv);
                }
            }
            float2 gir = upk2(iR), giz = upk2(iZ), gin = upk2(iN);
            float2 ghr = upk2(hR), ghz = upk2(hZ), ghn = upk2(hN);
            float bir = b_ih[l * G3 + j], biz = b_ih[l * G3 + Hd + j], bin = b_ih[l * G3 + 2 * Hd + j];
            float bhr = b_hh[l * G3 + j], bhz = b_hh[l * G3 + Hd + j], bhn = b_hh[l * G3 + 2 * Hd + j];
            float2 ho = *(const float2*)(hp + (size_t)j * Bsz + b0);
            float2 hn;
            {
                float r = sigm(gir.x + bir + ghr.x + bhr);
                float z = sigm(giz.x + biz + ghz.x + bhz);
                float n = tanhf(gin.x + bin + r * (ghn.x + bhn));
                hn.x = (1.0f - z) * n + z * ho.x;
            }
            {
                float r = sigm(gir.y + bir + ghr.y + bhr);
                float z = sigm(giz.y + biz + ghz.y + bhz);
                float n = tanhf(gin.y + bin + r * (ghn.y + bhn));
                hn.y = (1.0f - z) * n + z * ho.y;
            }
            *(float2*)(g_st[cur][l] + (size_t)j * Bsz + b0) = hn;
            gridbar();
        }
    }

    // ---------------- final output flush (step NSTEPS-1, state buf 0) ----------------
    {
        const float* h2 = g_st[0][2];   // (NSTEPS-1) & 1 == 0
        const float* w  = lin_W + (size_t)j * Hd;
        u64 acc = 0;
#pragma unroll 2
        for (int k = 0; k < Hd; k += 4) {
            float4 wv = *(const float4*)(w + k);
#pragma unroll
            for (int kk = 0; kk < 4; ++kk)
                fma2(acc, pk2(((const float*)&wv)[kk]),
                     *(const u64*)(h2 + (size_t)(k + kk) * Bsz + b0));
        }
        float2 t  = upk2(acc);
        float  bb = lin_b[j];
        size_t o0 = (size_t)b0 * NSTEPS * OD + (size_t)(NSTEPS - 1) * OD + j;
        out[o0]                       = t.x + bb;
        out[o0 + (size_t)NSTEPS * OD] = t.y + bb;
    }
}

extern "C" void kernel_launch(void* const* d_in, const int* in_sizes, int n_in,
                              void* d_out, int out_size) {
    (void)in_sizes; (void)n_in; (void)out_size;
    const int*   y          = (const int*)  d_in[0];
    // d_in[1] = U (unused by the reference math)
    const float* embed      = (const float*)d_in[2];
    const float* W_ih       = (const float*)d_in[3];
    const float* W_hh       = (const float*)d_in[4];
    const float* b_ih       = (const float*)d_in[5];
    const float* b_hh       = (const float*)d_in[6];
    const float* init_state = (const float*)d_in[7];
    const float* lin_W      = (const float*)d_in[8];
    const float* lin_b      = (const float*)d_in[9];
    float* out = (float*)d_out;

    decoder_kernel<<<NCTA, NTHR>>>(y, embed, W_ih, W_hh, b_ih, b_hh,
                                   init_state, lin_W, lin_b, out);
}

// round 3
// speedup vs baseline: 1.0572x; 1.0572x over previous
#include <cuda_runtime.h>
#include <cuda_bf16.h>

#define Bsz    64
#define Hd     1024
#define NV     101          // tokens incl. start symbol (start = 100)
#define UMX    256
#define NSTEPS 257
#define G3     3072         // 3*Hd
#define OD     1024
#define NCTA   128
#define NTHR   512
#define ETW    104          // embed-transpose padded width
#define KH     512          // k-half size (2-way k split)

typedef unsigned long long u64;

// ---------------- static device scratch (no runtime allocation) ----------------
__device__ __align__(16) float g_T[NV * G3];            // layer0 gi table (incl. b_ih0)
__device__ __align__(16) float g_ET[Hd * ETW];          // embed transposed [k][v]
__device__ __align__(16) float g_st[2][3][Hd * Bsz];    // states k-major: [buf][layer][k*64+b]
__device__ unsigned g_bar;                              // ticket barrier counter

// ---------------- grid barrier (all NCTA CTAs co-resident, 1/SM) ----------------
__device__ __forceinline__ void gridbar() {
    __syncthreads();
    if (threadIdx.x == 0) {
        __threadfence();
        unsigned ticket = atomicAdd(&g_bar, 1u) + 1u;
        unsigned target = ((ticket + NCTA - 1u) / NCTA) * NCTA;
        while (*((volatile unsigned*)&g_bar) < target) { __nanosleep(32); }
    }
    __syncthreads();
    __threadfence();
}

// ---------------- packed f32x2 helpers ----------------
__device__ __forceinline__ u64 pk2(float v) {
    u64 r;
    asm("mov.b64 %0, {%1, %1};" : "=l"(r) : "f"(v));
    return r;
}
__device__ __forceinline__ void fma2(u64& d, u64 a, u64 b) {
    asm("fma.rn.f32x2 %0, %1, %2, %0;" : "+l"(d) : "l"(a), "l"(b));
}
__device__ __forceinline__ float2 upk2(u64 v) {
    float lo, hi;
    asm("mov.b64 {%0, %1}, %2;" : "=f"(lo), "=f"(hi) : "l"(v));
    return make_float2(lo, hi);
}
__device__ __forceinline__ float sigm(float t) { return 1.0f / (1.0f + expf(-t)); }

// ================================================================================
__global__ void __launch_bounds__(NTHR, 1)
decoder_kernel(const int*   __restrict__ y,
               const float* __restrict__ embed,
               const float* __restrict__ W_ih,
               const float* __restrict__ W_hh,
               const float* __restrict__ b_ih,
               const float* __restrict__ b_hh,
               const float* __restrict__ init_state,
               const float* __restrict__ lin_W,
               const float* __restrict__ lin_b,
               float*       __restrict__ out)
{
    const int tid  = threadIdx.x;
    const int lane = tid & 31;
    const int wrp  = tid >> 5;            // 0..15
    const int wj   = wrp & 7;             // local row slot
    const int kh   = wrp >> 3;            // k-half: 0 or 1
    const int j    = (blockIdx.x << 3) + wj;   // 0..1023 hidden index
    const int k0   = kh * KH;
    const int b0   = lane << 1;           // batch pair base
    const int gt   = blockIdx.x * NTHR + tid;

    __shared__ u64 s_red[8][32][6];       // k-split reduction buffer (12 KB)

    // ---------------- prologue: init states + transpose embed ----------------
    for (int idx = gt; idx < 3 * Hd * Bsz; idx += NCTA * NTHR) {
        int l = idx / (Hd * Bsz);
        int r = idx - l * (Hd * Bsz);
        g_st[1][l][r] = init_state[l * Hd + (r >> 6)];
    }
    for (int idx = gt; idx < Hd * ETW; idx += NCTA * NTHR) {
        int k = idx / ETW, v = idx - k * ETW;
        g_ET[idx] = (v < NV) ? embed[(size_t)v * Hd + k] : 0.0f;
    }
    gridbar();

    // ---------------- token table: T[v][g*H+j] = embed[v].Wih0_row + b_ih0 ----------------
    {
        const int vp = lane + kh * 32;    // 0..63; active when vp < 52
        if (vp < ETW / 2) {
            const int v0 = vp << 1;
            const float* w0 = W_ih + (size_t)j * Hd;
            const float* w1 = W_ih + (size_t)(Hd + j) * Hd;
            const float* w2 = W_ih + (size_t)(2 * Hd + j) * Hd;
            u64 a0 = 0, a1 = 0, a2 = 0;
#pragma unroll 2
            for (int k = 0; k < Hd; k += 4) {
                float4 wa = *(const float4*)(w0 + k);
                float4 wb = *(const float4*)(w1 + k);
                float4 wc = *(const float4*)(w2 + k);
#pragma unroll
                for (int kk = 0; kk < 4; ++kk) {
                    u64 ev = *(const u64*)(g_ET + (size_t)(k + kk) * ETW + v0);
                    fma2(a0, pk2(((const float*)&wa)[kk]), ev);
                    fma2(a1, pk2(((const float*)&wb)[kk]), ev);
                    fma2(a2, pk2(((const float*)&wc)[kk]), ev);
                }
            }
            float2 t0 = upk2(a0), t1 = upk2(a1), t2 = upk2(a2);
            float br = b_ih[j], bz = b_ih[Hd + j], bn = b_ih[2 * Hd + j];
            if (v0 < NV) {
                g_T[(size_t)v0 * G3 + j]          = t0.x + br;
                g_T[(size_t)v0 * G3 + Hd + j]     = t1.x + bz;
                g_T[(size_t)v0 * G3 + 2 * Hd + j] = t2.x + bn;
            }
            if (v0 + 1 < NV) {
                g_T[(size_t)(v0 + 1) * G3 + j]          = t0.y + br;
                g_T[(size_t)(v0 + 1) * G3 + Hd + j]     = t1.y + bz;
                g_T[(size_t)(v0 + 1) * G3 + 2 * Hd + j] = t2.y + bn;
            }
        }
    }
    gridbar();

    // ---------------- autoregressive step loop ----------------
    for (int u = 0; u < NSTEPS; ++u) {
        const int cur = u & 1, prv = cur ^ 1;

        // ===== phase A: layer0 Whh GEMM + output linear of step u-1 (k-split) =====
        {
            const float* hp  = g_st[prv][0] + (size_t)k0 * Bsz + b0;
            const float* h2  = g_st[prv][2] + (size_t)k0 * Bsz + b0;
            const float* wr  = W_hh + (size_t)j * Hd + k0;
            const float* wz  = W_hh + (size_t)(Hd + j) * Hd + k0;
            const float* wn_ = W_hh + (size_t)(2 * Hd + j) * Hd + k0;
            const float* wo  = lin_W + (size_t)j * Hd + k0;
            u64 aR = 0, aZ = 0, aN = 0, aO = 0;
            float4 cr = *(const float4*)wr;
            float4 cz = *(const float4*)wz;
            float4 cn = *(const float4*)wn_;
            float4 co = *(const float4*)wo;
#pragma unroll 1
            for (int it = 0; it < KH / 4 - 1; ++it) {
                const int kb = it * 4;
                float4 nr = *(const float4*)(wr + kb + 4);
                float4 nz = *(const float4*)(wz + kb + 4);
                float4 nn = *(const float4*)(wn_ + kb + 4);
                float4 no = *(const float4*)(wo + kb + 4);
#pragma unroll
                for (int kk = 0; kk < 4; ++kk) {
                    u64 hv = *(const u64*)(hp + (size_t)(kb + kk) * Bsz);
                    u64 ov = *(const u64*)(h2 + (size_t)(kb + kk) * Bsz);
                    fma2(aR, pk2(((const float*)&cr)[kk]), hv);
                    fma2(aZ, pk2(((const float*)&cz)[kk]), hv);
                    fma2(aN, pk2(((const float*)&cn)[kk]), hv);
                    fma2(aO, pk2(((const float*)&co)[kk]), ov);
                }
                cr = nr; cz = nz; cn = nn; co = no;
            }
            {   // epilogue iteration kb = KH-4
                const int kb = KH - 4;
#pragma unroll
                for (int kk = 0; kk < 4; ++kk) {
                    u64 hv = *(const u64*)(hp + (size_t)(kb + kk) * Bsz);
                    u64 ov = *(const u64*)(h2 + (size_t)(kb + kk) * Bsz);
                    fma2(aR, pk2(((const float*)&cr)[kk]), hv);
                    fma2(aZ, pk2(((const float*)&cz)[kk]), hv);
                    fma2(aN, pk2(((const float*)&cn)[kk]), hv);
                    fma2(aO, pk2(((const float*)&co)[kk]), ov);
                }
            }
            if (kh == 1) {
                s_red[wj][lane][0] = aR; s_red[wj][lane][1] = aZ;
                s_red[wj][lane][2] = aN; s_red[wj][lane][3] = aO;
            }
            __syncthreads();
            if (kh == 0) {
                asm("add.rn.f32x2 %0, %0, %1;" : "+l"(aR) : "l"(s_red[wj][lane][0]));
                asm("add.rn.f32x2 %0, %0, %1;" : "+l"(aZ) : "l"(s_red[wj][lane][1]));
                asm("add.rn.f32x2 %0, %0, %1;" : "+l"(aN) : "l"(s_red[wj][lane][2]));
                asm("add.rn.f32x2 %0, %0, %1;" : "+l"(aO) : "l"(s_red[wj][lane][3]));
                int tk0 = (u == 0) ? (NV - 1) : y[b0 * UMX + (u - 1)];
                int tk1 = (u == 0) ? (NV - 1) : y[(b0 + 1) * UMX + (u - 1)];
                const float* T0 = g_T + (size_t)tk0 * G3 + j;
                const float* T1 = g_T + (size_t)tk1 * G3 + j;
                float2 ghr = upk2(aR), ghz = upk2(aZ), ghn = upk2(aN);
                float  bhr = b_hh[j], bhz = b_hh[Hd + j], bhn = b_hh[2 * Hd + j];
                float2 ho  = *(const float2*)(g_st[prv][0] + (size_t)j * Bsz + b0);
                float2 hn;
                {
                    float r = sigm(T0[0]       + ghr.x + bhr);
                    float z = sigm(T0[Hd]      + ghz.x + bhz);
                    float n = tanhf(T0[2 * Hd] + r * (ghn.x + bhn));
                    hn.x = (1.0f - z) * n + z * ho.x;
                }
                {
                    float r = sigm(T1[0]       + ghr.y + bhr);
                    float z = sigm(T1[Hd]      + ghz.y + bhz);
                    float n = tanhf(T1[2 * Hd] + r * (ghn.y + bhn));
                    hn.y = (1.0f - z) * n + z * ho.y;
                }
                *(float2*)(g_st[cur][0] + (size_t)j * Bsz + b0) = hn;
                if (u > 0) {
                    float2 t  = upk2(aO);
                    float  bb = lin_b[j];
                    size_t o0 = (size_t)b0 * NSTEPS * OD + (size_t)(u - 1) * OD + j;
                    out[o0]                       = t.x + bb;
                    out[o0 + (size_t)NSTEPS * OD] = t.y + bb;
                }
            }
        }
        gridbar();

        // ===== phases B, C: layers 1, 2 (full gi + gh GEMMs, k-split) =====
#pragma unroll 1
        for (int l = 1; l < 3; ++l) {
            const float* xx = g_st[cur][l - 1] + (size_t)k0 * Bsz + b0;
            const float* hp = g_st[prv][l]     + (size_t)k0 * Bsz + b0;
            const float* Wi = W_ih + (size_t)l * G3 * Hd;
            const float* Wh = W_hh + (size_t)l * G3 * Hd;
            const float* wi0 = Wi + (size_t)j * Hd + k0;
            const float* wi1 = Wi + (size_t)(Hd + j) * Hd + k0;
            const float* wi2 = Wi + (size_t)(2 * Hd + j) * Hd + k0;
            const float* wh0 = Wh + (size_t)j * Hd + k0;
            const float* wh1 = Wh + (size_t)(Hd + j) * Hd + k0;
            const float* wh2 = Wh + (size_t)(2 * Hd + j) * Hd + k0;
            u64 iR = 0, iZ = 0, iN = 0, hR = 0, hZ = 0, hN = 0;
            float4 ca = *(const float4*)wi0;
            float4 cb = *(const float4*)wi1;
            float4 cc = *(const float4*)wi2;
            float4 cd = *(const float4*)wh0;
            float4 ce = *(const float4*)wh1;
            float4 cf = *(const float4*)wh2;
#pragma unroll 1
            for (int it = 0; it < KH / 4 - 1; ++it) {
                const int kb = it * 4;
                float4 na = *(const float4*)(wi0 + kb + 4);
                float4 nb = *(const float4*)(wi1 + kb + 4);
                float4 nc = *(const float4*)(wi2 + kb + 4);
                float4 nd = *(const float4*)(wh0 + kb + 4);
                float4 ne = *(const float4*)(wh1 + kb + 4);
                float4 nf = *(const float4*)(wh2 + kb + 4);
#pragma unroll
                for (int kk = 0; kk < 4; ++kk) {
                    u64 xv = *(const u64*)(xx + (size_t)(kb + kk) * Bsz);
                    u64 hv = *(const u64*)(hp + (size_t)(kb + kk) * Bsz);
                    fma2(iR, pk2(((const float*)&ca)[kk]), xv);
                    fma2(iZ, pk2(((const float*)&cb)[kk]), xv);
                    fma2(iN, pk2(((const float*)&cc)[kk]), xv);
                    fma2(hR, pk2(((const float*)&cd)[kk]), hv);
                    fma2(hZ, pk2(((const float*)&ce)[kk]), hv);
                    fma2(hN, pk2(((const float*)&cf)[kk]), hv);
                }
                ca = na; cb = nb; cc = nc; cd = nd; ce = ne; cf = nf;
            }
            {   // epilogue iteration kb = KH-4
                const int kb = KH - 4;
#pragma unroll
                for (int kk = 0; kk < 4; ++kk) {
                    u64 xv = *(const u64*)(xx + (size_t)(kb + kk) * Bsz);
                    u64 hv = *(const u64*)(hp + (size_t)(kb + kk) * Bsz);
                    fma2(iR, pk2(((const float*)&ca)[kk]), xv);
                    fma2(iZ, pk2(((const float*)&cb)[kk]), xv);
                    fma2(iN, pk2(((const float*)&cc)[kk]), xv);
                    fma2(hR, pk2(((const float*)&cd)[kk]), hv);
                    fma2(hZ, pk2(((const float*)&ce)[kk]), hv);
                    fma2(hN, pk2(((const float*)&cf)[kk]), hv);
                }
            }
            if (kh == 1) {
                s_red[wj][lane][0] = iR; s_red[wj][lane][1] = iZ; s_red[wj][lane][2] = iN;
                s_red[wj][lane][3] = hR; s_red[wj][lane][4] = hZ; s_red[wj][lane][5] = hN;
            }
            __syncthreads();
            if (kh == 0) {
                asm("add.rn.f32x2 %0, %0, %1;" : "+l"(iR) : "l"(s_red[wj][lane][0]));
                asm("add.rn.f32x2 %0, %0, %1;" : "+l"(iZ) : "l"(s_red[wj][lane][1]));
                asm("add.rn.f32x2 %0, %0, %1;" : "+l"(iN) : "l"(s_red[wj][lane][2]));
                asm("add.rn.f32x2 %0, %0, %1;" : "+l"(hR) : "l"(s_red[wj][lane][3]));
                asm("add.rn.f32x2 %0, %0, %1;" : "+l"(hZ) : "l"(s_red[wj][lane][4]));
                asm("add.rn.f32x2 %0, %0, %1;" : "+l"(hN) : "l"(s_red[wj][lane][5]));
                float2 gir = upk2(iR), giz = upk2(iZ), gin = upk2(iN);
                float2 ghr = upk2(hR), ghz = upk2(hZ), ghn = upk2(hN);
                float bir = b_ih[l * G3 + j], biz = b_ih[l * G3 + Hd + j], bin = b_ih[l * G3 + 2 * Hd + j];
                float bhr = b_hh[l * G3 + j], bhz = b_hh[l * G3 + Hd + j], bhn = b_hh[l * G3 + 2 * Hd + j];
                float2 ho = *(const float2*)(g_st[prv][l] + (size_t)j * Bsz + b0);
                float2 hn;
                {
                    float r = sigm(gir.x + bir + ghr.x + bhr);
                    float z = sigm(giz.x + biz + ghz.x + bhz);
                    float n = tanhf(gin.x + bin + r * (ghn.x + bhn));
                    hn.x = (1.0f - z) * n + z * ho.x;
                }
                {
                    float r = sigm(gir.y + bir + ghr.y + bhr);
                    float z = sigm(giz.y + biz + ghz.y + bhz);
                    float n = tanhf(gin.y + bin + r * (ghn.y + bhn));
                    hn.y = (1.0f - z) * n + z * ho.y;
                }
                *(float2*)(g_st[cur][l] + (size_t)j * Bsz + b0) = hn;
            }
            gridbar();
        }
    }

    // ---------------- final output flush (step NSTEPS-1, state buf 0) ----------------
    {
        const float* h2 = g_st[0][2] + (size_t)k0 * Bsz + b0;   // (NSTEPS-1)&1 == 0
        const float* wo = lin_W + (size_t)j * Hd + k0;
        u64 aO = 0;
#pragma unroll 2
        for (int k = 0; k < KH; k += 4) {
            float4 wv = *(const float4*)(wo + k);
#pragma unroll
            for (int kk = 0; kk < 4; ++kk)
                fma2(aO, pk2(((const float*)&wv)[kk]),
                     *(const u64*)(h2 + (size_t)(k + kk) * Bsz));
        }
        if (kh == 1) s_red[wj][lane][0] = aO;
        __syncthreads();
        if (kh == 0) {
            asm("add.rn.f32x2 %0, %0, %1;" : "+l"(aO) : "l"(s_red[wj][lane][0]));
            float2 t  = upk2(aO);
            float  bb = lin_b[j];
            size_t o0 = (size_t)b0 * NSTEPS * OD + (size_t)(NSTEPS - 1) * OD + j;
            out[o0]                       = t.x + bb;
            out[o0 + (size_t)NSTEPS * OD] = t.y + bb;
        }
    }
}

extern "C" void kernel_launch(void* const* d_in, const int* in_sizes, int n_in,
                              void* d_out, int out_size) {
    (void)in_sizes; (void)n_in; (void)out_size;
    const int*   y          = (const int*)  d_in[0];
    // d_in[1] = U (unused by the reference math)
    const float* embed      = (const float*)d_in[2];
    const float* W_ih       = (const float*)d_in[3];
    const float* W_hh       = (const float*)d_in[4];
    const float* b_ih       = (const float*)d_in[5];
    const float* b_hh       = (const float*)d_in[6];
    const float* init_state = (const float*)d_in[7];
    const float* lin_W      = (const float*)d_in[8];
    const float* lin_b      = (const float*)d_in[9];
    float* out = (float*)d_out;

    decoder_kernel<<<NCTA, NTHR>>>(y, embed, W_ih, W_hh, b_ih, b_hh,
                                   init_state, lin_W, lin_b, out);
}